// round 16
// baseline (speedup 1.0000x reference)
#include <cuda_runtime.h>
#include <cuda_bf16.h>
#include <cuda_fp16.h>
#include <cstdint>
#include <math.h>

// ---------------------------------------------------------------------------
// HybridQCNNQLSTM : B=256, S=1024, H=256
//   Stage 1: per-element MLP 1->16->16->12->8->4->4 (tanh) -> 1 (linear)
//   Stage 2: LSTM via mma.sync m16n8k16 FP16 (W hi/lo x2 passes, fp32 acc),
//            H exchanged as single fp16 (4B st.async packets).
//            8 clusters x 8 CTAs, TWO warp-specialized streams per CTA.
//   out = [cnn_features (B*S) | logits (B)]
// ---------------------------------------------------------------------------

#define BATCH 256
#define SEQ   1024
#define HID   256

// ======================= Stage 1: CNN MLP kernel ===========================

template<int DIN, int DOUT>
__device__ __forceinline__ void layer_tanh(const float* __restrict__ w,
                                           const float* __restrict__ b,
                                           const float* in, float* out) {
#pragma unroll
    for (int o = 0; o < DOUT; ++o) {
        float s = b[o];
#pragma unroll
        for (int i = 0; i < DIN; ++i) s = fmaf(w[o * DIN + i], in[i], s);
        out[o] = tanhf(s);
    }
}

__global__ void __launch_bounds__(256) cnn_kernel(
    const float* __restrict__ x,
    const float* __restrict__ w1, const float* __restrict__ b1,
    const float* __restrict__ w2, const float* __restrict__ b2,
    const float* __restrict__ w3, const float* __restrict__ b3,
    const float* __restrict__ w4, const float* __restrict__ b4,
    const float* __restrict__ w5, const float* __restrict__ b5,
    const float* __restrict__ w6, const float* __restrict__ b6,
    const float* __restrict__ w7, const float* __restrict__ b7,
    float* __restrict__ out)
{
    __shared__ float ws[673];
    const int tid = threadIdx.x;
    {
        const float* srcs[14] = {w1,b1,w2,b2,w3,b3,w4,b4,w5,b5,w6,b6,w7,b7};
        const int    lens[14] = {16,16,256,16,192,12,96,8,32,4,16,4,4,1};
        int off = 0;
        for (int s = 0; s < 14; ++s) {
            for (int i = tid; i < lens[s]; i += 256) ws[off + i] = srcs[s][i];
            off += lens[s];
        }
    }
    __syncthreads();

    const int e = blockIdx.x * 256 + tid;
    float v = x[e];
    float h1[16], h2[16], h3[12], h4[8], h5[4], h6[4];
    layer_tanh<1, 16>(ws + 0,   ws + 16,  &v, h1);
    layer_tanh<16,16>(ws + 32,  ws + 288, h1, h2);
    layer_tanh<16,12>(ws + 304, ws + 496, h2, h3);
    layer_tanh<12, 8>(ws + 508, ws + 604, h3, h4);
    layer_tanh<8,  4>(ws + 612, ws + 644, h4, h5);
    layer_tanh<4,  4>(ws + 648, ws + 664, h5, h6);
    float o = ws[672];
#pragma unroll
    for (int i = 0; i < 4; ++i) o = fmaf(ws[668 + i], h6[i], o);
    out[e] = o;
}

// ======================= Stage 2: LSTM (dual-stream, fp16) =================

#define NB           16                     // batches per stream
#define NCLUST       8
#define LSTM_CTAS    64
#define LSTM_THREADS 512

#define ROW_BYTES   520                     // 16 kc * 32B + 8B pad (stride=2 mod 32 words)
#define BIMG_BYTES  (NB * ROW_BYTES)        // 8320
#define TX_BYTES    8192u                   // real data per image per phase
#define RED_STR     18
#define RED_BYTES   (128 * RED_STR * 4)     // 9216

// smem byte offsets
#define ALO_OFF    0                        // A-lo frags: 8*16*32*16 = 65536
#define BIMG_OFF   65536                    // 4 images (sid*2+buf) = 33280
#define RED_OFF    98816                    // 2 * 9216 = 18432
#define WXB_OFF    117248                   // [4][32] f32
#define BIAS_OFF   117760
#define XS_OFF     118272                   // 2 * 16 f32
#define MBAR_OFF   118400                   // 4 x 8B
#define SMEM_BYTES 118528

__device__ float g_hxf32[BATCH * HID];

__device__ __forceinline__ float fast_sigmoid(float v) {
    return __fdividef(1.0f, 1.0f + __expf(-v));
}
__device__ __forceinline__ float fast_tanh(float v) {
    return 1.0f - __fdividef(2.0f, __expf(2.0f * v) + 1.0f);
}
__device__ __forceinline__ uint32_t pack2h(float lo, float hi) {
    __half2 t = __floats2half2_rn(lo, hi);
    return *(uint32_t*)&t;
}

__device__ __forceinline__ void mma16816(float* c, const uint32_t* a,
                                         uint32_t b0, uint32_t b1) {
    asm volatile(
        "mma.sync.aligned.m16n8k16.row.col.f32.f16.f16.f32 "
        "{%0,%1,%2,%3}, {%4,%5,%6,%7}, {%8,%9}, {%0,%1,%2,%3};"
        : "+f"(c[0]), "+f"(c[1]), "+f"(c[2]), "+f"(c[3])
        : "r"(a[0]), "r"(a[1]), "r"(a[2]), "r"(a[3]), "r"(b0), "r"(b1));
}

#define CLUSTER_SYNC_() do { \
    asm volatile("barrier.cluster.arrive.aligned;" ::: "memory"); \
    asm volatile("barrier.cluster.wait.aligned;"   ::: "memory"); \
} while (0)

#define FENCE_CLUSTER_() asm volatile("fence.acq_rel.cluster;" ::: "memory")

#define BAR_STREAM(sid) \
    asm volatile("bar.sync %0, 256;" :: "r"((sid) + 1) : "memory")

#define MBARRIER_INIT(mbar, cnt) \
    asm volatile("mbarrier.init.shared.b64 [%0], %1;" \
        :: "r"((uint32_t)(mbar)), "r"((uint32_t)(cnt)) : "memory")

#define MBAR_EXPECT_TX(mbar, bytes) \
    asm volatile("mbarrier.arrive.expect_tx.shared.b64 _, [%0], %1;" \
        :: "r"((uint32_t)(mbar)), "r"((uint32_t)(bytes)) : "memory")

#define MBAR_WAIT_PARITY(mbar, par) do { \
    uint32_t _m = (uint32_t)(mbar); uint32_t _p = (uint32_t)(par); uint32_t _d; \
    asm volatile("{\n\t.reg .pred p;\n\t" \
        "mbarrier.try_wait.parity.acquire.cta.shared::cta.b64 p, [%1], %2;\n\t" \
        "selp.b32 %0, 1, 0, p;\n\t}" : "=r"(_d) : "r"(_m), "r"(_p) : "memory"); \
    if (!_d) { \
        asm volatile("{\n\t.reg .pred P1;\n\t" \
            "WL_%=:\n\t" \
            "mbarrier.try_wait.parity.acquire.cta.shared::cta.b64 P1, [%0], %1, 0x989680;\n\t" \
            "@P1 bra.uni WD_%=;\n\t" \
            "bra.uni WL_%=;\n\t" \
            "WD_%=:\n\t}" :: "r"(_m), "r"(_p) : "memory"); \
    } \
} while(0)

// async DSMEM store: 4B payload + transaction completion on remote mbarrier
#define ST_ASYNC_B32(daddr, val, mbaddr) \
    asm volatile("st.async.weak.shared::cluster.mbarrier::complete_tx::bytes.b32 [%0], %1, [%2];" \
        :: "r"((uint32_t)(daddr)), "r"((uint32_t)(val)), "r"((uint32_t)(mbaddr)) : "memory")

__global__ void __launch_bounds__(LSTM_THREADS, 1) __cluster_dims__(8, 1, 1)
lstm_kernel(const float* __restrict__ xfeat,
            const float* __restrict__ w_f, const float* __restrict__ b_f,
            const float* __restrict__ w_i, const float* __restrict__ b_i,
            const float* __restrict__ w_g, const float* __restrict__ b_g,
            const float* __restrict__ w_o, const float* __restrict__ b_o,
            const float* __restrict__ w_head, const float* __restrict__ b_head,
            float* __restrict__ logits)
{
    extern __shared__ __align__(16) uint8_t sm8[];
    float* wxb_sm  = (float*)(sm8 + WXB_OFF);
    float* bias_sm = (float*)(sm8 + BIAS_OFF);

    uint32_t smem_u32;
    asm("{ .reg .u64 t; cvta.to.shared.u64 t, %1; cvt.u32.u64 %0, t; }"
        : "=r"(smem_u32) : "l"(sm8));

    const int tid     = threadIdx.x;
    const int warp    = tid >> 5;
    const int lane    = tid & 31;
    const int sid     = warp >> 3;      // stream 0/1
    const int sw      = warp & 7;       // stream-local warp = mrow
    const int stid    = tid & 255;      // stream-local thread
    const int ctarank = blockIdx.x & 7;
    const int clust   = blockIdx.x >> 3;
    const int h0      = ctarank * 32;
    const int b0s     = clust * 32 + sid * NB;

    float* redS = (float*)(sm8 + RED_OFF + sid * RED_BYTES);
    float* xsS  = (float*)(sm8 + XS_OFF) + sid * NB;

    const float* Wg[4] = {w_f, w_i, w_g, w_o};
    const float* Bg[4] = {b_f, b_i, b_g, b_o};

    if (tid < 128) {
        int g = tid >> 5, h = tid & 31;
        wxb_sm[g * 32 + h]  = Wg[g][(h0 + h) * 257];
        bias_sm[g * 32 + h] = Bg[g][h0 + h];
    }
    if (tid < 4) MBARRIER_INIT(smem_u32 + MBAR_OFF + tid * 8, 1);

    // ---- build A-hi frags in regs (fp16, full K); A-lo (fp16, subnormal
    //      residuals) into smem (stream 0 writes; both streams read)
    uint32_t ahi[64];
    {
        const int r0 = sw * 16 + (lane >> 2);
        const int r1 = r0 + 8;
        const float* row0 = Wg[r0 >> 5] + (h0 + (r0 & 31)) * 257 + 1;
        const float* row1 = Wg[r1 >> 5] + (h0 + (r1 & 31)) * 257 + 1;
        const int kb = (lane & 3) * 2;
#pragma unroll
        for (int kc = 0; kc < 16; ++kc) {
            int k0 = kc * 16 + kb;
            float v00 = row0[k0],     v01 = row0[k0 + 1];
            float v10 = row1[k0],     v11 = row1[k0 + 1];
            float v02 = row0[k0 + 8], v03 = row0[k0 + 9];
            float v12 = row1[k0 + 8], v13 = row1[k0 + 9];
            float h00 = __half2float(__float2half_rn(v00));
            float h01 = __half2float(__float2half_rn(v01));
            float h10 = __half2float(__float2half_rn(v10));
            float h11 = __half2float(__float2half_rn(v11));
            float h02 = __half2float(__float2half_rn(v02));
            float h03 = __half2float(__float2half_rn(v03));
            float h12 = __half2float(__float2half_rn(v12));
            float h13 = __half2float(__float2half_rn(v13));
            ahi[kc * 4 + 0] = pack2h(h00, h01);
            ahi[kc * 4 + 1] = pack2h(h10, h11);
            ahi[kc * 4 + 2] = pack2h(h02, h03);
            ahi[kc * 4 + 3] = pack2h(h12, h13);
            if (sid == 0) {
                uint4 lo4;
                lo4.x = pack2h(v00 - h00, v01 - h01);
                lo4.y = pack2h(v10 - h10, v11 - h11);
                lo4.z = pack2h(v02 - h02, v03 - h03);
                lo4.w = pack2h(v12 - h12, v13 - h13);
                *(uint4*)(sm8 + ALO_OFF + ((sw * 16 + kc) * 32 + lane) * 16) = lo4;
            }
        }
    }

    // ---- zero par=0 B images of both streams
    {
        uint32_t zero = 0;
        uint32_t* b00 = (uint32_t*)(sm8 + BIMG_OFF);                   // sid0 buf0
        uint32_t* b10 = (uint32_t*)(sm8 + BIMG_OFF + 2 * BIMG_BYTES);  // sid1 buf0
        for (int i = tid; i < BIMG_BYTES / 4; i += LSTM_THREADS) {
            b00[i] = zero; b10[i] = zero;
        }
    }
    __syncthreads();
    // pre-loop expect for buffer 1 phase 0 (filled by pushes during t=0)
    if (stid == 0) MBAR_EXPECT_TX(smem_u32 + MBAR_OFF + (sid * 2 + 1) * 8, TX_BYTES);
    __syncthreads();
    CLUSTER_SYNC_();   // images, mbar inits+expect, A-lo visible cluster-wide

    // epilogue constants (per stream thread)
    const int ep_b  = stid >> 4;    // 0..15
    const int ep_hp = stid & 15;
    // word position inside the 32B kc-chunk: interleaved {k01,k89,k23,k10-11,...}
    const int ep_kc = ctarank * 2 + (ep_hp >> 3);
    const int ep_j2 = ep_hp & 7;
    const int ep_w  = (ep_j2 < 4) ? (ep_j2 * 2) : ((ep_j2 - 4) * 2 + 1);
    const uint32_t ep_off = (uint32_t)(ep_b * ROW_BYTES + ep_kc * 32 + ep_w * 4);

    // precompute remote data/mbar addresses for buf=1; buf=0 = -BIMG_BYTES/-8
    uint32_t dstA[8], mbA[8];
#pragma unroll
    for (int r = 0; r < 8; ++r) {
        uint32_t dl = smem_u32 + BIMG_OFF + (sid * 2 + 1) * BIMG_BYTES + ep_off;
        uint32_t ml = smem_u32 + MBAR_OFF + (sid * 2 + 1) * 8;
        asm("mapa.shared::cluster.u32 %0, %1, %2;" : "=r"(dstA[r]) : "r"(dl), "r"(r));
        asm("mapa.shared::cluster.u32 %0, %1, %2;" : "=r"(mbA[r])  : "r"(ml), "r"(r));
    }

    float cx[2] = {0.f, 0.f};

#pragma unroll 1
    for (int t = 0; t < SEQ; ++t) {
        const int par = t & 1;
        const uint32_t ph = (uint32_t)(((t - 1) >> 1) & 1);
        const uint32_t mb_rd = smem_u32 + MBAR_OFF + (sid * 2 + par) * 8;

        if (stid < NB) xsS[stid] = __ldg(xfeat + (b0s + stid) * SEQ + t);

        if (t > 0) MBAR_WAIT_PARITY(mb_rd, ph);
        // re-arm this buffer's next phase BEFORE our own pushes of this step
        if (stid == 0) MBAR_EXPECT_TX(mb_rd, TX_BYTES);

        // ---- MMA: this stream's B image; full K per warp, 2 n-tiles, 2 passes
        const uint8_t* bimg = sm8 + BIMG_OFF + (sid * 2 + par) * BIMG_BYTES;
        float acc0[4] = {0.f,0.f,0.f,0.f};
        float acc1[4] = {0.f,0.f,0.f,0.f};
        {
            const uint8_t* bp = bimg + (lane >> 2) * ROW_BYTES + (lane & 3) * 8;
            const uint4* alp = (const uint4*)(sm8 + ALO_OFF) + (sw * 16) * 32 + lane;
#pragma unroll
            for (int kc = 0; kc < 16; ++kc) {
                uint2 p0 = *(const uint2*)(bp + kc * 32);
                uint2 p1 = *(const uint2*)(bp + 8 * ROW_BYTES + kc * 32);
                uint4 al = alp[kc * 32];
                mma16816(acc0, ahi + kc * 4, p0.x, p0.y);          // Whi*H
                mma16816(acc1, ahi + kc * 4, p1.x, p1.y);
                mma16816(acc0, (const uint32_t*)&al, p0.x, p0.y);  // Wlo*H
                mma16816(acc1, (const uint32_t*)&al, p1.x, p1.y);
            }
        }

        // ---- gate transpose into stream red
        {
            const int r0 = sw * 16 + (lane >> 2);
            const int c0 = (lane & 3) * 2;
            *(float2*)(redS + r0 * RED_STR + c0)           = make_float2(acc0[0], acc0[1]);
            *(float2*)(redS + (r0 + 8) * RED_STR + c0)     = make_float2(acc0[2], acc0[3]);
            *(float2*)(redS + r0 * RED_STR + 8 + c0)       = make_float2(acc1[0], acc1[1]);
            *(float2*)(redS + (r0 + 8) * RED_STR + 8 + c0) = make_float2(acc1[2], acc1[3]);
        }
        BAR_STREAM(sid);

        // ---- epilogue: gates -> cx/hx -> st.async push into all 8 B[par^1]
        {
            float xb = xsS[ep_b];
            float vout[2];
#pragma unroll
            for (int j = 0; j < 2; ++j) {
                int h = ep_hp * 2 + j;
                float pf = redS[(0*32 + h) * RED_STR + ep_b] + fmaf(wxb_sm[0*32+h], xb, bias_sm[0*32+h]);
                float pi = redS[(1*32 + h) * RED_STR + ep_b] + fmaf(wxb_sm[1*32+h], xb, bias_sm[1*32+h]);
                float pg = redS[(2*32 + h) * RED_STR + ep_b] + fmaf(wxb_sm[2*32+h], xb, bias_sm[2*32+h]);
                float po = redS[(3*32 + h) * RED_STR + ep_b] + fmaf(wxb_sm[3*32+h], xb, bias_sm[3*32+h]);
                float f  = fast_sigmoid(pf);
                float ii = fast_sigmoid(pi);
                float gg = fast_tanh(pg);
                float oo = fast_sigmoid(po);
                cx[j] = fmaf(f, cx[j], ii * gg);
                vout[j] = oo * fast_tanh(cx[j]);
            }
            uint32_t pkt = pack2h(vout[0], vout[1]);

            const uint32_t dadj = par ? (uint32_t)BIMG_BYTES : 0u;  // buf=par^1
            const uint32_t madj = par ? 8u : 0u;
#pragma unroll
            for (int r = 0; r < 8; ++r)
                ST_ASYNC_B32(dstA[r] - dadj, pkt, mbA[r] - madj);

            if (t == SEQ - 1)
                *(float2*)(g_hxf32 + (b0s + ep_b) * HID + h0 + ep_hp * 2) =
                    make_float2(vout[0], vout[1]);
        }
        // destination mbarrier byte-count provides completion + backpressure
    }

    FENCE_CLUSTER_();
    CLUSTER_SYNC_();

    // ---- head (rank-0 CTA): logits for the cluster's 32 batches
    if (ctarank == 0 && tid < 256) {
        const int bb   = tid >> 3;
        const int part = tid & 7;
        const float* src = g_hxf32 + (clust * 32 + bb) * HID + part * 32;
        float s = 0.0f;
#pragma unroll
        for (int kk = 0; kk < 32; ++kk)
            s = fmaf(src[kk], __ldg(w_head + part * 32 + kk), s);
        s += __shfl_xor_sync(0xffffffffu, s, 4);
        s += __shfl_xor_sync(0xffffffffu, s, 2);
        s += __shfl_xor_sync(0xffffffffu, s, 1);
        if (part == 0) logits[clust * 32 + bb] = s + __ldg(b_head);
    }
}

// ======================= launch ===========================================

extern "C" void kernel_launch(void* const* d_in, const int* in_sizes, int n_in,
                              void* d_out, int out_size)
{
    const float* x      = (const float*)d_in[0];
    const float* w1     = (const float*)d_in[1];
    const float* b1     = (const float*)d_in[2];
    const float* w2     = (const float*)d_in[3];
    const float* b2     = (const float*)d_in[4];
    const float* w3     = (const float*)d_in[5];
    const float* b3     = (const float*)d_in[6];
    const float* w4     = (const float*)d_in[7];
    const float* b4     = (const float*)d_in[8];
    const float* w5     = (const float*)d_in[9];
    const float* b5     = (const float*)d_in[10];
    const float* w6     = (const float*)d_in[11];
    const float* b6     = (const float*)d_in[12];
    const float* w7     = (const float*)d_in[13];
    const float* b7     = (const float*)d_in[14];
    const float* w_f    = (const float*)d_in[15];
    const float* b_f    = (const float*)d_in[16];
    const float* w_i    = (const float*)d_in[17];
    const float* b_i    = (const float*)d_in[18];
    const float* w_g    = (const float*)d_in[19];
    const float* b_g    = (const float*)d_in[20];
    const float* w_o    = (const float*)d_in[21];
    const float* b_o    = (const float*)d_in[22];
    const float* w_head = (const float*)d_in[23];
    const float* b_head = (const float*)d_in[24];

    float* out = (float*)d_out;

    cnn_kernel<<<(BATCH * SEQ) / 256, 256>>>(x, w1, b1, w2, b2, w3, b3, w4, b4,
                                             w5, b5, w6, b6, w7, b7, out);

    cudaFuncSetAttribute(lstm_kernel, cudaFuncAttributeMaxDynamicSharedMemorySize,
                         SMEM_BYTES);
    lstm_kernel<<<LSTM_CTAS, LSTM_THREADS, SMEM_BYTES>>>(
        out, w_f, b_f, w_i, b_i, w_g, b_g, w_o, b_o, w_head, b_head,
        out + BATCH * SEQ);
}

// round 17
// speedup vs baseline: 1.4520x; 1.4520x over previous
#include <cuda_runtime.h>
#include <cuda_bf16.h>
#include <cuda_fp16.h>
#include <cstdint>
#include <math.h>

// ---------------------------------------------------------------------------
// HybridQCNNQLSTM : B=256, S=1024, H=256
//   Stage 1: per-element MLP 1->16->16->12->8->4->4 (tanh) -> 1 (linear)
//   Stage 2: LSTM via mma.sync m16n8k16 FP16 (W hi/lo x2 passes, fp32 acc),
//            H exchanged as single fp16 (4B st.async packets).
//            B image: kc-paired 16B packets, conflict-free 528B row stride.
//            8 clusters x 8 CTAs, TWO warp-specialized streams per CTA.
//   out = [cnn_features (B*S) | logits (B)]
// ---------------------------------------------------------------------------

#define BATCH 256
#define SEQ   1024
#define HID   256

// ======================= Stage 1: CNN MLP kernel ===========================

template<int DIN, int DOUT>
__device__ __forceinline__ void layer_tanh(const float* __restrict__ w,
                                           const float* __restrict__ b,
                                           const float* in, float* out) {
#pragma unroll
    for (int o = 0; o < DOUT; ++o) {
        float s = b[o];
#pragma unroll
        for (int i = 0; i < DIN; ++i) s = fmaf(w[o * DIN + i], in[i], s);
        out[o] = tanhf(s);
    }
}

__global__ void __launch_bounds__(256) cnn_kernel(
    const float* __restrict__ x,
    const float* __restrict__ w1, const float* __restrict__ b1,
    const float* __restrict__ w2, const float* __restrict__ b2,
    const float* __restrict__ w3, const float* __restrict__ b3,
    const float* __restrict__ w4, const float* __restrict__ b4,
    const float* __restrict__ w5, const float* __restrict__ b5,
    const float* __restrict__ w6, const float* __restrict__ b6,
    const float* __restrict__ w7, const float* __restrict__ b7,
    float* __restrict__ out)
{
    __shared__ float ws[673];
    const int tid = threadIdx.x;
    {
        const float* srcs[14] = {w1,b1,w2,b2,w3,b3,w4,b4,w5,b5,w6,b6,w7,b7};
        const int    lens[14] = {16,16,256,16,192,12,96,8,32,4,16,4,4,1};
        int off = 0;
        for (int s = 0; s < 14; ++s) {
            for (int i = tid; i < lens[s]; i += 256) ws[off + i] = srcs[s][i];
            off += lens[s];
        }
    }
    __syncthreads();

    const int e = blockIdx.x * 256 + tid;
    float v = x[e];
    float h1[16], h2[16], h3[12], h4[8], h5[4], h6[4];
    layer_tanh<1, 16>(ws + 0,   ws + 16,  &v, h1);
    layer_tanh<16,16>(ws + 32,  ws + 288, h1, h2);
    layer_tanh<16,12>(ws + 304, ws + 496, h2, h3);
    layer_tanh<12, 8>(ws + 508, ws + 604, h3, h4);
    layer_tanh<8,  4>(ws + 612, ws + 644, h4, h5);
    layer_tanh<4,  4>(ws + 648, ws + 664, h5, h6);
    float o = ws[672];
#pragma unroll
    for (int i = 0; i < 4; ++i) o = fmaf(ws[668 + i], h6[i], o);
    out[e] = o;
}

// ======================= Stage 2: LSTM (dual-stream, fp16 v2) ==============

#define NB           16                     // batches per stream
#define NCLUST       8
#define LSTM_CTAS    64
#define LSTM_THREADS 512

#define ROW_BYTES   528                     // 8 kcp * 64B + 16B pad (132 words = 4 mod 32)
#define BIMG_BYTES  (NB * ROW_BYTES)        // 8448
#define TX_BYTES    8192u                   // real data per image per phase
#define RED_STR     18
#define RED_BYTES   (128 * RED_STR * 4)     // 9216

// smem byte offsets
#define ALO_OFF    0                        // A-lo frags: 8*16*32*16 = 65536
#define BIMG_OFF   65536                    // 4 images (sid*2+buf) = 33792
#define RED_OFF    99328                    // 2 * 9216 = 18432
#define WXB_OFF    117760                   // [4][32] f32
#define BIAS_OFF   118272
#define XS_OFF     118784                   // 2 * 16 f32
#define MBAR_OFF   118912                   // 4 x 8B
#define SMEM_BYTES 119040

__device__ float g_hxf32[BATCH * HID];

__device__ __forceinline__ float fast_sigmoid(float v) {
    return __fdividef(1.0f, 1.0f + __expf(-v));
}
__device__ __forceinline__ float fast_tanh(float v) {
    return 1.0f - __fdividef(2.0f, __expf(2.0f * v) + 1.0f);
}
__device__ __forceinline__ uint32_t pack2h(float lo, float hi) {
    __half2 t = __floats2half2_rn(lo, hi);
    return *(uint32_t*)&t;
}

__device__ __forceinline__ void mma16816(float* c, const uint32_t* a,
                                         uint32_t b0, uint32_t b1) {
    asm volatile(
        "mma.sync.aligned.m16n8k16.row.col.f32.f16.f16.f32 "
        "{%0,%1,%2,%3}, {%4,%5,%6,%7}, {%8,%9}, {%0,%1,%2,%3};"
        : "+f"(c[0]), "+f"(c[1]), "+f"(c[2]), "+f"(c[3])
        : "r"(a[0]), "r"(a[1]), "r"(a[2]), "r"(a[3]), "r"(b0), "r"(b1));
}

#define CLUSTER_SYNC_() do { \
    asm volatile("barrier.cluster.arrive.aligned;" ::: "memory"); \
    asm volatile("barrier.cluster.wait.aligned;"   ::: "memory"); \
} while (0)

#define FENCE_CLUSTER_() asm volatile("fence.acq_rel.cluster;" ::: "memory")

#define BAR_STREAM(sid) \
    asm volatile("bar.sync %0, 256;" :: "r"((sid) + 1) : "memory")

#define MBARRIER_INIT(mbar, cnt) \
    asm volatile("mbarrier.init.shared.b64 [%0], %1;" \
        :: "r"((uint32_t)(mbar)), "r"((uint32_t)(cnt)) : "memory")

#define MBAR_EXPECT_TX(mbar, bytes) \
    asm volatile("mbarrier.arrive.expect_tx.shared.b64 _, [%0], %1;" \
        :: "r"((uint32_t)(mbar)), "r"((uint32_t)(bytes)) : "memory")

#define MBAR_WAIT_PARITY(mbar, par) do { \
    uint32_t _m = (uint32_t)(mbar); uint32_t _p = (uint32_t)(par); uint32_t _d; \
    asm volatile("{\n\t.reg .pred p;\n\t" \
        "mbarrier.try_wait.parity.acquire.cta.shared::cta.b64 p, [%1], %2;\n\t" \
        "selp.b32 %0, 1, 0, p;\n\t}" : "=r"(_d) : "r"(_m), "r"(_p) : "memory"); \
    if (!_d) { \
        asm volatile("{\n\t.reg .pred P1;\n\t" \
            "WL_%=:\n\t" \
            "mbarrier.try_wait.parity.acquire.cta.shared::cta.b64 P1, [%0], %1, 0x989680;\n\t" \
            "@P1 bra.uni WD_%=;\n\t" \
            "bra.uni WL_%=;\n\t" \
            "WD_%=:\n\t}" :: "r"(_m), "r"(_p) : "memory"); \
    } \
} while(0)

// async DSMEM store: 4B payload + transaction completion on remote mbarrier
#define ST_ASYNC_B32(daddr, val, mbaddr) \
    asm volatile("st.async.weak.shared::cluster.mbarrier::complete_tx::bytes.b32 [%0], %1, [%2];" \
        :: "r"((uint32_t)(daddr)), "r"((uint32_t)(val)), "r"((uint32_t)(mbaddr)) : "memory")

__global__ void __launch_bounds__(LSTM_THREADS, 1) __cluster_dims__(8, 1, 1)
lstm_kernel(const float* __restrict__ xfeat,
            const float* __restrict__ w_f, const float* __restrict__ b_f,
            const float* __restrict__ w_i, const float* __restrict__ b_i,
            const float* __restrict__ w_g, const float* __restrict__ b_g,
            const float* __restrict__ w_o, const float* __restrict__ b_o,
            const float* __restrict__ w_head, const float* __restrict__ b_head,
            float* __restrict__ logits)
{
    extern __shared__ __align__(16) uint8_t sm8[];
    float* wxb_sm  = (float*)(sm8 + WXB_OFF);
    float* bias_sm = (float*)(sm8 + BIAS_OFF);

    uint32_t smem_u32;
    asm("{ .reg .u64 t; cvta.to.shared.u64 t, %1; cvt.u32.u64 %0, t; }"
        : "=r"(smem_u32) : "l"(sm8));

    const int tid     = threadIdx.x;
    const int warp    = tid >> 5;
    const int lane    = tid & 31;
    const int sid     = warp >> 3;      // stream 0/1
    const int sw      = warp & 7;       // stream-local warp = mrow
    const int stid    = tid & 255;      // stream-local thread
    const int ctarank = blockIdx.x & 7;
    const int clust   = blockIdx.x >> 3;
    const int h0      = ctarank * 32;
    const int b0s     = clust * 32 + sid * NB;

    float* redS = (float*)(sm8 + RED_OFF + sid * RED_BYTES);
    float* xsS  = (float*)(sm8 + XS_OFF) + sid * NB;

    const float* Wg[4] = {w_f, w_i, w_g, w_o};
    const float* Bg[4] = {b_f, b_i, b_g, b_o};

    if (tid < 128) {
        int g = tid >> 5, h = tid & 31;
        wxb_sm[g * 32 + h]  = Wg[g][(h0 + h) * 257];
        bias_sm[g * 32 + h] = Bg[g][h0 + h];
    }
    if (tid < 4) MBARRIER_INIT(smem_u32 + MBAR_OFF + tid * 8, 1);

    // ---- build A-hi frags in regs (fp16, full K); A-lo (fp16 residuals,
    //      subnormal range) into smem (stream 0 writes; both streams read)
    uint32_t ahi[64];
    {
        const int r0 = sw * 16 + (lane >> 2);
        const int r1 = r0 + 8;
        const float* row0 = Wg[r0 >> 5] + (h0 + (r0 & 31)) * 257 + 1;
        const float* row1 = Wg[r1 >> 5] + (h0 + (r1 & 31)) * 257 + 1;
        const int kb = (lane & 3) * 2;
#pragma unroll
        for (int kc = 0; kc < 16; ++kc) {
            int k0 = kc * 16 + kb;
            float v00 = row0[k0],     v01 = row0[k0 + 1];
            float v10 = row1[k0],     v11 = row1[k0 + 1];
            float v02 = row0[k0 + 8], v03 = row0[k0 + 9];
            float v12 = row1[k0 + 8], v13 = row1[k0 + 9];
            float h00 = __half2float(__float2half_rn(v00));
            float h01 = __half2float(__float2half_rn(v01));
            float h10 = __half2float(__float2half_rn(v10));
            float h11 = __half2float(__float2half_rn(v11));
            float h02 = __half2float(__float2half_rn(v02));
            float h03 = __half2float(__float2half_rn(v03));
            float h12 = __half2float(__float2half_rn(v12));
            float h13 = __half2float(__float2half_rn(v13));
            ahi[kc * 4 + 0] = pack2h(h00, h01);
            ahi[kc * 4 + 1] = pack2h(h10, h11);
            ahi[kc * 4 + 2] = pack2h(h02, h03);
            ahi[kc * 4 + 3] = pack2h(h12, h13);
            if (sid == 0) {
                uint4 lo4;
                lo4.x = pack2h(v00 - h00, v01 - h01);
                lo4.y = pack2h(v10 - h10, v11 - h11);
                lo4.z = pack2h(v02 - h02, v03 - h03);
                lo4.w = pack2h(v12 - h12, v13 - h13);
                *(uint4*)(sm8 + ALO_OFF + ((sw * 16 + kc) * 32 + lane) * 16) = lo4;
            }
        }
    }

    // ---- zero buf=0 B images of both streams
    {
        uint32_t zero = 0;
        uint32_t* b00 = (uint32_t*)(sm8 + BIMG_OFF);                   // sid0 buf0
        uint32_t* b10 = (uint32_t*)(sm8 + BIMG_OFF + 2 * BIMG_BYTES);  // sid1 buf0
        for (int i = tid; i < BIMG_BYTES / 4; i += LSTM_THREADS) {
            b00[i] = zero; b10[i] = zero;
        }
    }
    __syncthreads();
    // pre-loop expect for buffer 1 phase 0 (filled by pushes during t=0)
    if (stid == 0) MBAR_EXPECT_TX(smem_u32 + MBAR_OFF + (sid * 2 + 1) * 8, TX_BYTES);
    __syncthreads();
    CLUSTER_SYNC_();   // images, mbar inits+expect, A-lo visible cluster-wide

    // epilogue constants (per stream thread)
    const int ep_b  = stid >> 4;    // 0..15 (image n row)
    const int ep_hp = stid & 15;    // h pair (2*ep_hp, 2*ep_hp+1) local
    // B image slot for k pair (h0 + 2*ep_hp, +1):
    //   image[n][kcp][c] uint4 = {W0(2kcp), W1(2kcp), W0(2kcp+1), W1(2kcp+1)}
    //   W0(kc) = k{2c,2c+1}, W1(kc) = k{2c+8,2c+9} within 16-chunk kc
    const int ep_kg  = h0 + ep_hp * 2;        // global k (even)
    const int ep_kc  = ep_kg >> 4;
    const int ep_r16 = ep_kg & 15;
    const int ep_half = (ep_r16 >= 8) ? 1 : 0;
    const int ep_c    = (ep_half ? (ep_r16 - 8) : ep_r16) >> 1;
    const int ep_word = 2 * (ep_kc & 1) + ep_half;
    const uint32_t ep_off = (uint32_t)(ep_b * ROW_BYTES + (ep_kc >> 1) * 64
                                       + ep_c * 16 + ep_word * 4);

    // precompute remote data/mbar addresses for buf=1; buf=0 = -BIMG_BYTES/-8
    uint32_t dstA[8], mbA[8];
#pragma unroll
    for (int r = 0; r < 8; ++r) {
        uint32_t dl = smem_u32 + BIMG_OFF + (sid * 2 + 1) * BIMG_BYTES + ep_off;
        uint32_t ml = smem_u32 + MBAR_OFF + (sid * 2 + 1) * 8;
        asm("mapa.shared::cluster.u32 %0, %1, %2;" : "=r"(dstA[r]) : "r"(dl), "r"(r));
        asm("mapa.shared::cluster.u32 %0, %1, %2;" : "=r"(mbA[r])  : "r"(ml), "r"(r));
    }

    float cx[2] = {0.f, 0.f};

#pragma unroll 1
    for (int t = 0; t < SEQ; ++t) {
        const int par = t & 1;
        const uint32_t ph = (uint32_t)(((t - 1) >> 1) & 1);
        const uint32_t mb_rd = smem_u32 + MBAR_OFF + (sid * 2 + par) * 8;

        if (stid < NB) xsS[stid] = __ldg(xfeat + (b0s + stid) * SEQ + t);

        if (t > 0) MBAR_WAIT_PARITY(mb_rd, ph);
        // re-arm this buffer's next phase BEFORE our own pushes of this step
        if (stid == 0) MBAR_EXPECT_TX(mb_rd, TX_BYTES);

        // ---- MMA: this stream's B image; full K per warp, 2 n-tiles, 2 passes
        const uint8_t* bimg = sm8 + BIMG_OFF + (sid * 2 + par) * BIMG_BYTES;
        float acc0[4] = {0.f,0.f,0.f,0.f};
        float acc1[4] = {0.f,0.f,0.f,0.f};
        {
            const uint8_t* bp = bimg + (lane >> 2) * ROW_BYTES + (lane & 3) * 16;
            const uint4* alp = (const uint4*)(sm8 + ALO_OFF) + (sw * 16) * 32 + lane;
#pragma unroll
            for (int kcp = 0; kcp < 8; ++kcp) {
                uint4 q0 = *(const uint4*)(bp + kcp * 64);
                uint4 q1 = *(const uint4*)(bp + 8 * ROW_BYTES + kcp * 64);
                uint4 al0 = alp[(2 * kcp) * 32];
                uint4 al1 = alp[(2 * kcp + 1) * 32];
                // kc = 2*kcp : fragment (q.x, q.y)
                mma16816(acc0, ahi + (2 * kcp) * 4, q0.x, q0.y);        // Whi*H
                mma16816(acc1, ahi + (2 * kcp) * 4, q1.x, q1.y);
                mma16816(acc0, (const uint32_t*)&al0, q0.x, q0.y);      // Wlo*H
                mma16816(acc1, (const uint32_t*)&al0, q1.x, q1.y);
                // kc = 2*kcp+1 : fragment (q.z, q.w)
                mma16816(acc0, ahi + (2 * kcp + 1) * 4, q0.z, q0.w);
                mma16816(acc1, ahi + (2 * kcp + 1) * 4, q1.z, q1.w);
                mma16816(acc0, (const uint32_t*)&al1, q0.z, q0.w);
                mma16816(acc1, (const uint32_t*)&al1, q1.z, q1.w);
            }
        }

        // ---- gate transpose into stream red
        {
            const int r0 = sw * 16 + (lane >> 2);
            const int c0 = (lane & 3) * 2;
            *(float2*)(redS + r0 * RED_STR + c0)           = make_float2(acc0[0], acc0[1]);
            *(float2*)(redS + (r0 + 8) * RED_STR + c0)     = make_float2(acc0[2], acc0[3]);
            *(float2*)(redS + r0 * RED_STR + 8 + c0)       = make_float2(acc1[0], acc1[1]);
            *(float2*)(redS + (r0 + 8) * RED_STR + 8 + c0) = make_float2(acc1[2], acc1[3]);
        }
        BAR_STREAM(sid);

        // ---- epilogue: gates -> cx/hx -> st.async push into all 8 B[par^1]
        {
            float xb = xsS[ep_b];
            float vout[2];
#pragma unroll
            for (int j = 0; j < 2; ++j) {
                int h = ep_hp * 2 + j;
                float pf = redS[(0*32 + h) * RED_STR + ep_b] + fmaf(wxb_sm[0*32+h], xb, bias_sm[0*32+h]);
                float pi = redS[(1*32 + h) * RED_STR + ep_b] + fmaf(wxb_sm[1*32+h], xb, bias_sm[1*32+h]);
                float pg = redS[(2*32 + h) * RED_STR + ep_b] + fmaf(wxb_sm[2*32+h], xb, bias_sm[2*32+h]);
                float po = redS[(3*32 + h) * RED_STR + ep_b] + fmaf(wxb_sm[3*32+h], xb, bias_sm[3*32+h]);
                float f  = fast_sigmoid(pf);
                float ii = fast_sigmoid(pi);
                float gg = fast_tanh(pg);
                float oo = fast_sigmoid(po);
                cx[j] = fmaf(f, cx[j], ii * gg);
                vout[j] = oo * fast_tanh(cx[j]);
            }
            uint32_t pkt = pack2h(vout[0], vout[1]);

            const uint32_t dadj = par ? (uint32_t)BIMG_BYTES : 0u;  // buf=par^1
            const uint32_t madj = par ? 8u : 0u;
#pragma unroll
            for (int r = 0; r < 8; ++r)
                ST_ASYNC_B32(dstA[r] - dadj, pkt, mbA[r] - madj);

            if (t == SEQ - 1)
                *(float2*)(g_hxf32 + (b0s + ep_b) * HID + h0 + ep_hp * 2) =
                    make_float2(vout[0], vout[1]);
        }
        // destination mbarrier byte-count provides completion + backpressure
    }

    FENCE_CLUSTER_();
    CLUSTER_SYNC_();

    // ---- head (rank-0 CTA): logits for the cluster's 32 batches
    if (ctarank == 0 && tid < 256) {
        const int bb   = tid >> 3;
        const int part = tid & 7;
        const float* src = g_hxf32 + (clust * 32 + bb) * HID + part * 32;
        float s = 0.0f;
#pragma unroll
        for (int kk = 0; kk < 32; ++kk)
            s = fmaf(src[kk], __ldg(w_head + part * 32 + kk), s);
        s += __shfl_xor_sync(0xffffffffu, s, 4);
        s += __shfl_xor_sync(0xffffffffu, s, 2);
        s += __shfl_xor_sync(0xffffffffu, s, 1);
        if (part == 0) logits[clust * 32 + bb] = s + __ldg(b_head);
    }
}

// ======================= launch ===========================================

extern "C" void kernel_launch(void* const* d_in, const int* in_sizes, int n_in,
                              void* d_out, int out_size)
{
    const float* x      = (const float*)d_in[0];
    const float* w1     = (const float*)d_in[1];
    const float* b1     = (const float*)d_in[2];
    const float* w2     = (const float*)d_in[3];
    const float* b2     = (const float*)d_in[4];
    const float* w3     = (const float*)d_in[5];
    const float* b3     = (const float*)d_in[6];
    const float* w4     = (const float*)d_in[7];
    const float* b4     = (const float*)d_in[8];
    const float* w5     = (const float*)d_in[9];
    const float* b5     = (const float*)d_in[10];
    const float* w6     = (const float*)d_in[11];
    const float* b6     = (const float*)d_in[12];
    const float* w7     = (const float*)d_in[13];
    const float* b7     = (const float*)d_in[14];
    const float* w_f    = (const float*)d_in[15];
    const float* b_f    = (const float*)d_in[16];
    const float* w_i    = (const float*)d_in[17];
    const float* b_i    = (const float*)d_in[18];
    const float* w_g    = (const float*)d_in[19];
    const float* b_g    = (const float*)d_in[20];
    const float* w_o    = (const float*)d_in[21];
    const float* b_o    = (const float*)d_in[22];
    const float* w_head = (const float*)d_in[23];
    const float* b_head = (const float*)d_in[24];

    float* out = (float*)d_out;

    cnn_kernel<<<(BATCH * SEQ) / 256, 256>>>(x, w1, b1, w2, b2, w3, b3, w4, b4,
                                             w5, b5, w6, b6, w7, b7, out);

    cudaFuncSetAttribute(lstm_kernel, cudaFuncAttributeMaxDynamicSharedMemorySize,
                         SMEM_BYTES);
    lstm_kernel<<<LSTM_CTAS, LSTM_THREADS, SMEM_BYTES>>>(
        out, w_f, b_f, w_i, b_i, w_g, b_g, w_o, b_o, w_head, b_head,
        out + BATCH * SEQ);
}